// round 1
// baseline (speedup 1.0000x reference)
#include <cuda_runtime.h>
#include <cuda_bf16.h>
#include <cstdint>

// MaxUnpooling2DMod: out[b, y(idx), x(idx), c] += in[b,h,w,c]
// out shape [8, 256, 256, 64]  (flat 2^25 floats)
// in  shape [8, 128, 128, 64]  (flat 2^23 floats)
// decode: out_off = (b << 22) + (idx & ~63) + (lin & 63)
//   because y*W_out*C + x*C == (idx / C) * C == idx & ~(C-1), and f == input channel.

static constexpr int N_TOTAL = 8 * 128 * 128 * 64;   // 8,388,608 = 2^23
static constexpr int PER_BATCH_SHIFT = 20;           // 128*128*64 = 2^20
static constexpr int OUT_BATCH_SHIFT = 22;           // 256*256*64 = 2^22

__global__ void __launch_bounds__(256)
unpool_scatter_kernel(const float* __restrict__ in,
                      const int*   __restrict__ idx,
                      float*       __restrict__ out)
{
    int t = blockIdx.x * blockDim.x + threadIdx.x;   // one thread per 4 elements
    int i = t << 2;                                   // linear element index (multiple of 4)
    if (i >= N_TOTAL) return;

    // Vectorized 16B loads: 2 LDG.128 per thread, MLP-friendly.
    float4 v  = reinterpret_cast<const float4*>(in)[t];
    int4   id = reinterpret_cast<const int4*>(idx)[t];

    int base = (i >> PER_BATCH_SHIFT) << OUT_BATCH_SHIFT;  // b * 2^22
    int c    = i & 63;                                      // channel of elem 0 (c..c+3 same 4-group)

    // REDG (no-return atomic add) to global; addresses are effectively random
    // within this batch's 16 MB output slab.
    atomicAdd(out + base + (id.x & ~63) + (c + 0), v.x);
    atomicAdd(out + base + (id.y & ~63) + (c + 1), v.y);
    atomicAdd(out + base + (id.z & ~63) + (c + 2), v.z);
    atomicAdd(out + base + (id.w & ~63) + (c + 3), v.w);
}

extern "C" void kernel_launch(void* const* d_in, const int* in_sizes, int n_in,
                              void* d_out, int out_size)
{
    const float* in   = (const float*)d_in[0];
    const int*   idx  = (const int*)d_in[1];
    float*       out  = (float*)d_out;

    // Zero the output (scatter-add semantics; d_out is poisoned before timing).
    cudaMemsetAsync(out, 0, (size_t)out_size * sizeof(float), 0);

    int n_threads = N_TOTAL / 4;                 // 2,097,152
    int block = 256;
    int grid  = (n_threads + block - 1) / block; // 8192
    unpool_scatter_kernel<<<grid, block>>>(in, idx, out);
}

// round 2
// speedup vs baseline: 1.3057x; 1.3057x over previous
#include <cuda_runtime.h>
#include <cuda_bf16.h>
#include <cstdint>

// MaxUnpooling2DMod: out[b, y(idx), x(idx), c] += in[b,h,w,c]
//   in  [8,128,128,64]  -> 2^23 floats
//   out [8,256,256,64]  -> 2^25 floats
// decode: out_off = (b << 22) + (idx & ~63) + (lin & 63)
//
// Pipeline: kernel k_b scatters batch b (into slab b, which the PREVIOUS
// kernel just zeroed -> L2-resident atomics) and concurrently zeros slab b+1
// (disjoint range, pure STG bandwidth hidden under the atomic-bound scatter).

static constexpr int ELEMS_PER_BATCH   = 1 << 20;   // 128*128*64
static constexpr int SLAB_FLOATS       = 1 << 22;   // 256*256*64
static constexpr int BLOCK             = 256;
static constexpr int GRID              = 2048;
static constexpr int THREADS_TOTAL     = GRID * BLOCK;            // 524288
static constexpr int SLAB_F4           = SLAB_FLOATS / 4;         // 1048576 float4
static constexpr int F4_PER_THREAD     = SLAB_F4 / THREADS_TOTAL; // 2
static constexpr int ELEMS_PER_THREAD  = ELEMS_PER_BATCH / THREADS_TOTAL; // 2

__global__ void __launch_bounds__(BLOCK)
unpool_fused_kernel(const float* __restrict__ in,
                    const int*   __restrict__ idx,
                    float*       __restrict__ out,
                    int b_scatter,   // batch to scatter, -1 = none
                    int b_zero)      // slab to zero,     -1 = none
{
    const int tid = blockIdx.x * BLOCK + threadIdx.x;

    // ---- scatter loads first (long-latency, get them in flight) ----
    float2 v;
    int2   id;
    int    e0 = 0;
    if (b_scatter >= 0) {
        e0 = b_scatter * ELEMS_PER_BATCH + tid * ELEMS_PER_THREAD;
        v  = reinterpret_cast<const float2*>(in)[e0 >> 1];
        id = reinterpret_cast<const int2*>(idx)[e0 >> 1];
    }

    // ---- zero slab b_zero (disjoint from scatter target slab) ----
    if (b_zero >= 0) {
        float4* o4 = reinterpret_cast<float4*>(out) + (size_t)b_zero * SLAB_F4;
        const float4 z = make_float4(0.f, 0.f, 0.f, 0.f);
        #pragma unroll
        for (int j = 0; j < F4_PER_THREAD; j++)
            o4[tid + j * THREADS_TOTAL] = z;
    }

    // ---- scatter: 2 REDG per thread into L2-hot slab ----
    if (b_scatter >= 0) {
        const int base = b_scatter << 22;        // slab base (2^22 floats)
        const int c0   = e0 & 63;                // channel of elem 0 (even)
        atomicAdd(out + base + (id.x & ~63) + c0,       v.x);
        atomicAdd(out + base + (id.y & ~63) + (c0 + 1), v.y);
    }
}

extern "C" void kernel_launch(void* const* d_in, const int* in_sizes, int n_in,
                              void* d_out, int out_size)
{
    const float* in  = (const float*)d_in[0];
    const int*   idx = (const int*)d_in[1];
    float*       out = (float*)d_out;

    // Prologue: zero slab 0 only.
    unpool_fused_kernel<<<GRID, BLOCK>>>(in, idx, out, -1, 0);
    // Steady state: scatter batch b (slab b is L2-hot from previous kernel),
    // zero slab b+1 under it.
    for (int b = 0; b < 8; b++)
        unpool_fused_kernel<<<GRID, BLOCK>>>(in, idx, out, b, b < 7 ? b + 1 : -1);
}